// round 2
// baseline (speedup 1.0000x reference)
#include <cuda_runtime.h>
#include <cstdint>
#include <cstddef>

#define NB 1024
#define NT 512
#define NH 128
#define NG 512   // 4*H

// ---------------- scratch (device globals; no runtime allocation) ----------------
__device__ float g_h0[(size_t)NB * NT * NH];   // layer0 output  [B][T][H]
__device__ float g_h1[(size_t)NB * NT * NH];   // layer1 output  [B][T][H]
__device__ float g_hlast[NB * NH];             // layer2 last-step h
// Packed pair layout: flat float idx = (((kk*2+half)*128)+u)*4 + comp
//   comp&1 = k parity (k = 2*kk + (comp&1)), comp>>1 selects gate q = 2*half + (comp>>1)
__device__ float g_WT[3][256 * NG];
__device__ float g_bias[3][NG];                // [u][4] gate order i,f,g,o

// ---------------- weight transpose / pack ----------------
__global__ void prep_kernel(const float* __restrict__ w_ih, const float* __restrict__ w_hh,
                            const float* __restrict__ b_ih, const float* __restrict__ b_hh,
                            int layer, int din, int kp)
{
    float* WT = g_WT[layer];
    int total = kp * NG;   // kp/2 kk-pairs * 2 halves * 128 u * 4 comps
    for (int idx = blockIdx.x * blockDim.x + threadIdx.x; idx < total;
         idx += gridDim.x * blockDim.x) {
        int comp = idx & 3;
        int u    = (idx >> 2) & (NH - 1);
        int half = (idx >> 9) & 1;
        int kk   = idx >> 10;
        int k    = 2 * kk + (comp & 1);
        int q    = 2 * half + (comp >> 1);
        int g    = q * NH + u;
        float val = 0.0f;
        if (k < din)            val = w_ih[g * din + k];
        else if (k < din + NH)  val = w_hh[g * NH + (k - din)];
        WT[idx] = val;
    }
    for (int g = blockIdx.x * blockDim.x + threadIdx.x; g < NG;
         g += gridDim.x * blockDim.x) {
        int q = g / NH, u = g % NH;
        g_bias[layer][u * 4 + q] = b_ih[g] + b_hh[g];
    }
}

// ---------------- f32x2 helpers ----------------
__device__ __forceinline__ unsigned long long pack2(float lo, float hi) {
    unsigned long long r;
    asm("mov.b64 %0, {%1, %2};" : "=l"(r) : "f"(lo), "f"(hi));
    return r;
}
__device__ __forceinline__ float hsum2(unsigned long long a) {
    float lo, hi;
    asm("mov.b64 {%0, %1}, %2;" : "=f"(lo), "=f"(hi) : "l"(a));
    return lo + hi;
}
__device__ __forceinline__ unsigned long long fma2(unsigned long long a,
                                                   unsigned long long b,
                                                   unsigned long long c) {
    unsigned long long d;
    asm("fma.rn.f32x2 %0, %1, %2, %3;" : "=l"(d) : "l"(a), "l"(b), "l"(c));
    return d;
}

// ---------------- activations (HW MUFU.TANH) ----------------
__device__ __forceinline__ float fast_tanh(float x) {
    float y;
    asm("tanh.approx.f32 %0, %1;" : "=f"(y) : "f"(x));
    return y;
}
__device__ __forceinline__ float fast_sig(float x) {
    return fmaf(0.5f, fast_tanh(0.5f * x), 0.5f);
}

// ---------------- LSTM layer: one CTA = 8 batch rows, loops all T internally ------
// thread tile: unit u = tid&127, batch-half bh = tid>>7 -> 4 gates x 4 batches
// f32x2-packed along K; double-buffered smem, ONE syncthreads per step.
template <int DIN>
__global__ void __launch_bounds__(256)
lstm_layer_kernel(const float* __restrict__ xin,  // [B][T][DIN]
                  float* __restrict__ hout,       // [B][T][H] or nullptr
                  float* __restrict__ hlast,      // [B][H]   or nullptr
                  int layer)
{
    constexpr int K    = DIN + NH;
    constexpr int KP   = (K + 3) & ~3;      // 136 (layer0) / 256 (layers 1,2)
    constexpr int NKK2 = KP / 4;            // 34 / 64 blocks of 4 k-values
    __shared__ __align__(16) float v[2][8][KP];

    const ulonglong2* __restrict__ WT = reinterpret_cast<const ulonglong2*>(g_WT[layer]);

    const int tid = threadIdx.x;
    const int u   = tid & (NH - 1);
    const int bh  = tid >> 7;             // 0 or 1
    const int b0  = blockIdx.x * 8;
    const int bb  = b0 + bh * 4;

    const float4 bias4 = *reinterpret_cast<const float4*>(&g_bias[layer][u * 4]);
    const unsigned long long bp[4] = {
        pack2(bias4.x, 0.f), pack2(bias4.y, 0.f),
        pack2(bias4.z, 0.f), pack2(bias4.w, 0.f)
    };

    // zero both buffers (h regions + pads)
    for (int i = tid; i < 2 * 8 * KP; i += 256) (&v[0][0][0])[i] = 0.0f;

    // stage x_0 into buffer 0
    if (DIN == 128) {
        int b = tid >> 5, k4 = (tid & 31) * 4;
        *reinterpret_cast<float4*>(&v[0][b][k4]) =
            *reinterpret_cast<const float4*>(&xin[((size_t)(b0 + b) * NT + 0) * DIN + k4]);
    } else {
        if (tid < 8 * DIN) {
            int b = tid / DIN, k = tid - b * DIN;
            v[0][b][k] = xin[((size_t)(b0 + b) * NT + 0) * DIN + k];
        }
    }
    __syncthreads();

    float c[4] = {0.f, 0.f, 0.f, 0.f};
    int p = 0;

    for (int t = 0; t < NT; ++t) {
        // ---- prefetch x_{t+1} into registers (overlaps with FFMA block) ----
        float4 xr = {0.f, 0.f, 0.f, 0.f};
        const bool havex = (t + 1 < NT);
        int xb = 0, xk = 0;
        if (DIN == 128) {
            xb = tid >> 5; xk = (tid & 31) * 4;
            if (havex)
                xr = *reinterpret_cast<const float4*>(
                    &xin[((size_t)(b0 + xb) * NT + (t + 1)) * DIN + xk]);
        } else {
            if (havex && tid < 8 * DIN) {
                xb = tid / DIN; xk = tid - xb * DIN;
                xr.x = xin[((size_t)(b0 + xb) * NT + (t + 1)) * DIN + xk];
            }
        }

        // ---- gates = bias + W * [x_t ; h_{t-1}]  (f32x2-packed along K) ----
        unsigned long long acc[4][4];
#pragma unroll
        for (int j = 0; j < 4; ++j) {
            acc[j][0] = bp[0]; acc[j][1] = bp[1];
            acc[j][2] = bp[2]; acc[j][3] = bp[3];
        }

        const float* vrow0 = v[p][bh * 4 + 0];
        const float* vrow1 = v[p][bh * 4 + 1];
        const float* vrow2 = v[p][bh * 4 + 2];
        const float* vrow3 = v[p][bh * 4 + 3];

#pragma unroll 4
        for (int kk2 = 0; kk2 < NKK2; ++kk2) {
            // weights: 4 x LDG.128, each = two f32x2 operands (gate pairs)
            ulonglong2 wA0 = WT[(size_t)(4 * kk2 + 0) * NH + u];  // kk even: gates 0,1
            ulonglong2 wB0 = WT[(size_t)(4 * kk2 + 1) * NH + u];  // kk even: gates 2,3
            ulonglong2 wA1 = WT[(size_t)(4 * kk2 + 2) * NH + u];  // kk odd : gates 0,1
            ulonglong2 wB1 = WT[(size_t)(4 * kk2 + 3) * NH + u];  // kk odd : gates 2,3
            // x: one broadcast LDS.128 per batch = two f32x2 operands
            ulonglong2 x0 = *reinterpret_cast<const ulonglong2*>(vrow0 + 4 * kk2);
            ulonglong2 x1 = *reinterpret_cast<const ulonglong2*>(vrow1 + 4 * kk2);
            ulonglong2 x2 = *reinterpret_cast<const ulonglong2*>(vrow2 + 4 * kk2);
            ulonglong2 x3 = *reinterpret_cast<const ulonglong2*>(vrow3 + 4 * kk2);

#define STEP2(j, xv)                                   \
            acc[j][0] = fma2(wA0.x, xv.x, acc[j][0]);  \
            acc[j][1] = fma2(wA0.y, xv.x, acc[j][1]);  \
            acc[j][2] = fma2(wB0.x, xv.x, acc[j][2]);  \
            acc[j][3] = fma2(wB0.y, xv.x, acc[j][3]);  \
            acc[j][0] = fma2(wA1.x, xv.y, acc[j][0]);  \
            acc[j][1] = fma2(wA1.y, xv.y, acc[j][1]);  \
            acc[j][2] = fma2(wB1.x, xv.y, acc[j][2]);  \
            acc[j][3] = fma2(wB1.y, xv.y, acc[j][3]);
            STEP2(0, x0)
            STEP2(1, x1)
            STEP2(2, x2)
            STEP2(3, x3)
#undef STEP2
        }

        // ---- pointwise LSTM cell ----
        float hn[4];
#pragma unroll
        for (int j = 0; j < 4; ++j) {
            float ii = fast_sig(hsum2(acc[j][0]));
            float ff = fast_sig(hsum2(acc[j][1]));
            float gg = fast_tanh(hsum2(acc[j][2]));
            float oo = fast_sig(hsum2(acc[j][3]));
            float cn = fmaf(ff, c[j], ii * gg);
            c[j] = cn;
            hn[j] = oo * fast_tanh(cn);
        }

        // ---- fill next buffer: x_{t+1} + h_t (no sync needed before writes) ----
        float* nv = &v[1 - p][0][0];
        if (DIN == 128) {
            if (havex)
                *reinterpret_cast<float4*>(nv + (size_t)xb * KP + xk) = xr;
        } else {
            if (havex && tid < 8 * DIN)
                nv[(size_t)xb * KP + xk] = xr.x;
        }
#pragma unroll
        for (int j = 0; j < 4; ++j)
            nv[(size_t)(bh * 4 + j) * KP + DIN + u] = hn[j];

        if (hout) {
#pragma unroll
            for (int j = 0; j < 4; ++j)
                hout[((size_t)(bb + j) * NT + t) * NH + u] = hn[j];
        }
        if (hlast && t == NT - 1) {
#pragma unroll
            for (int j = 0; j < 4; ++j)
                hlast[(bb + j) * NH + u] = hn[j];
        }

        __syncthreads();
        p ^= 1;
    }
}

// ---------------- final FC on last timestep of layer 2 ----------------
__global__ void fc_kernel(const float* __restrict__ fc_w,
                          const float* __restrict__ fc_b,
                          float* __restrict__ out)
{
    int b = blockIdx.x;
    int tid = threadIdx.x;           // 128 threads, one per unit
    float p = g_hlast[b * NH + tid] * fc_w[tid];
#pragma unroll
    for (int o = 16; o; o >>= 1) p += __shfl_down_sync(0xffffffffu, p, o);
    __shared__ float ws[4];
    if ((tid & 31) == 0) ws[tid >> 5] = p;
    __syncthreads();
    if (tid == 0) out[b] = ws[0] + ws[1] + ws[2] + ws[3] + fc_b[0];
}

// ---------------- launch ----------------
extern "C" void kernel_launch(void* const* d_in, const int* in_sizes, int n_in,
                              void* d_out, int out_size)
{
    const float* x    = (const float*)d_in[0];
    const float* wih0 = (const float*)d_in[1];
    const float* whh0 = (const float*)d_in[2];
    const float* bih0 = (const float*)d_in[3];
    const float* bhh0 = (const float*)d_in[4];
    const float* wih1 = (const float*)d_in[5];
    const float* whh1 = (const float*)d_in[6];
    const float* bih1 = (const float*)d_in[7];
    const float* bhh1 = (const float*)d_in[8];
    const float* wih2 = (const float*)d_in[9];
    const float* whh2 = (const float*)d_in[10];
    const float* bih2 = (const float*)d_in[11];
    const float* bhh2 = (const float*)d_in[12];
    const float* fcw  = (const float*)d_in[13];
    const float* fcb  = (const float*)d_in[14];
    float* out = (float*)d_out;

    void *ph0 = nullptr, *ph1 = nullptr, *phl = nullptr;
    cudaGetSymbolAddress(&ph0, g_h0);
    cudaGetSymbolAddress(&ph1, g_h1);
    cudaGetSymbolAddress(&phl, g_hlast);

    prep_kernel<<<132, 256>>>(wih0, whh0, bih0, bhh0, 0, 6,   136);
    prep_kernel<<<132, 256>>>(wih1, whh1, bih1, bhh1, 1, 128, 256);
    prep_kernel<<<132, 256>>>(wih2, whh2, bih2, bhh2, 2, 128, 256);

    lstm_layer_kernel<6>  <<<NB / 8, 256>>>(x, (float*)ph0, nullptr, 0);
    lstm_layer_kernel<128><<<NB / 8, 256>>>((const float*)ph0, (float*)ph1, nullptr, 1);
    lstm_layer_kernel<128><<<NB / 8, 256>>>((const float*)ph1, nullptr, (float*)phl, 2);

    fc_kernel<<<NB, 128>>>(fcw, fcb, out);
}

// round 3
// speedup vs baseline: 1.3590x; 1.3590x over previous
#include <cuda_runtime.h>
#include <cstdint>
#include <cstddef>

#define NB 1024
#define NT 512
#define NH 128
#define NG 512   // 4*H

// ---------------- scratch (device globals; no runtime allocation) ----------------
__device__ float g_h0[(size_t)NB * NT * NH];   // layer0 output  [B][T][H]
__device__ float g_h1[(size_t)NB * NT * NH];   // layer1 output  [B][T][H]
__device__ float g_hlast[NB * NH];             // layer2 last-step h
__device__ float g_WT[3][256 * NG];            // per layer: [k][u][4] (i,f,g,o packed)
__device__ float g_bias[3][NG];                // per layer: [u][4]

// ---------------- weight transpose / pack ----------------
// WT[k][u][q] = (k < din) ? w_ih[q*H+u][k] : w_hh[q*H+u][k-din];  zeros for k >= din+H
__global__ void prep_kernel(const float* __restrict__ w_ih, const float* __restrict__ w_hh,
                            const float* __restrict__ b_ih, const float* __restrict__ b_hh,
                            int layer, int din, int kp)
{
    float* WT = g_WT[layer];
    int total = kp * NG;
    for (int idx = blockIdx.x * blockDim.x + threadIdx.x; idx < total;
         idx += gridDim.x * blockDim.x) {
        int q = idx & 3;
        int u = (idx >> 2) & (NH - 1);
        int k = idx >> 9;
        int g = q * NH + u;
        float val = 0.0f;
        if (k < din)            val = w_ih[g * din + k];
        else if (k < din + NH)  val = w_hh[g * NH + (k - din)];
        WT[idx] = val;
    }
    for (int g = blockIdx.x * blockDim.x + threadIdx.x; g < NG;
         g += gridDim.x * blockDim.x) {
        int q = g / NH, u = g % NH;
        g_bias[layer][u * 4 + q] = b_ih[g] + b_hh[g];
    }
}

// ---------------- activations (HW MUFU.TANH) ----------------
__device__ __forceinline__ float fast_tanh(float x) {
    float y;
    asm("tanh.approx.f32 %0, %1;" : "=f"(y) : "f"(x));
    return y;
}
__device__ __forceinline__ float fast_sig(float x) {
    return fmaf(0.5f, fast_tanh(0.5f * x), 0.5f);
}

#define ACC4(j, xv)                                                                     \
    acc[j][0] = fmaf(w0.x, xv.x, fmaf(w1.x, xv.y, fmaf(w2.x, xv.z, fmaf(w3.x, xv.w, acc[j][0])))); \
    acc[j][1] = fmaf(w0.y, xv.x, fmaf(w1.y, xv.y, fmaf(w2.y, xv.z, fmaf(w3.y, xv.w, acc[j][1])))); \
    acc[j][2] = fmaf(w0.z, xv.x, fmaf(w1.z, xv.y, fmaf(w2.z, xv.z, fmaf(w3.z, xv.w, acc[j][2])))); \
    acc[j][3] = fmaf(w0.w, xv.x, fmaf(w1.w, xv.y, fmaf(w2.w, xv.z, fmaf(w3.w, xv.w, acc[j][3]))));

// ---------------- LSTM layer: one CTA = 8 batch rows, 512 threads, all T in-loop ---
// thread tile: unit u = tid&127, group grp = tid>>7 (0..3) -> 4 gates x 2 batches
// Double-buffered smem v, ONE syncthreads per step; x_{t+1} prefetched in regs.
template <int DIN>
__global__ void __launch_bounds__(512, 1)
lstm_layer_kernel(const float* __restrict__ xin,  // [B][T][DIN]
                  float* __restrict__ hout,       // [B][T][H] or nullptr
                  float* __restrict__ hlast,      // [B][H]   or nullptr
                  int layer)
{
    constexpr int K  = DIN + NH;
    constexpr int KP = (K + 3) & ~3;      // 136 (layer0) / 256 (layers 1,2)
    __shared__ __align__(16) float v[2][8][KP];

    const float4* __restrict__ WT4 = reinterpret_cast<const float4*>(g_WT[layer]);

    const int tid = threadIdx.x;
    const int u   = tid & (NH - 1);
    const int grp = tid >> 7;             // 0..3
    const int b0  = blockIdx.x * 8;
    const int bb  = b0 + grp * 2;         // this thread's 2 batches: bb, bb+1

    const float4 bias4 = *reinterpret_cast<const float4*>(&g_bias[layer][u * 4]);

    // zero both buffers (h regions + pads must start at 0)
    for (int i = tid; i < 2 * 8 * KP; i += 512) (&v[0][0][0])[i] = 0.0f;

    // stage x_0 into buffer 0
    if (DIN == 128) {
        int b = tid >> 6, k2 = (tid & 63) * 2;
        *reinterpret_cast<float2*>(&v[0][b][k2]) =
            *reinterpret_cast<const float2*>(&xin[((size_t)(b0 + b) * NT + 0) * DIN + k2]);
    } else {
        if (tid < 8 * DIN) {
            int b = tid / DIN, k = tid - b * DIN;
            v[0][b][k] = xin[((size_t)(b0 + b) * NT + 0) * DIN + k];
        }
    }
    __syncthreads();

    float c[2] = {0.f, 0.f};
    int p = 0;

    for (int t = 0; t < NT; ++t) {
        // ---- prefetch x_{t+1} into registers (overlaps FFMA block) ----
        float2 xr = {0.f, 0.f};
        const bool havex = (t + 1 < NT);
        int xb = 0, xk = 0;
        if (DIN == 128) {
            xb = tid >> 6; xk = (tid & 63) * 2;
            if (havex)
                xr = *reinterpret_cast<const float2*>(
                    &xin[((size_t)(b0 + xb) * NT + (t + 1)) * DIN + xk]);
        } else {
            if (havex && tid < 8 * DIN) {
                xb = tid / DIN; xk = tid - xb * DIN;
                xr.x = xin[((size_t)(b0 + xb) * NT + (t + 1)) * DIN + xk];
            }
        }

        // ---- gates = bias + W * [x_t ; h_{t-1}] ----
        float acc[2][4];
#pragma unroll
        for (int j = 0; j < 2; ++j) {
            acc[j][0] = bias4.x; acc[j][1] = bias4.y;
            acc[j][2] = bias4.z; acc[j][3] = bias4.w;
        }

        const float* vr0 = v[p][grp * 2 + 0];
        const float* vr1 = v[p][grp * 2 + 1];

#pragma unroll 4
        for (int k = 0; k < KP; k += 4) {
            float4 w0 = WT4[(size_t)(k + 0) * NH + u];
            float4 w1 = WT4[(size_t)(k + 1) * NH + u];
            float4 w2 = WT4[(size_t)(k + 2) * NH + u];
            float4 w3 = WT4[(size_t)(k + 3) * NH + u];
            float4 x0 = *reinterpret_cast<const float4*>(vr0 + k);
            float4 x1 = *reinterpret_cast<const float4*>(vr1 + k);
            ACC4(0, x0)
            ACC4(1, x1)
        }

        // ---- pointwise LSTM cell ----
        float hn[2];
#pragma unroll
        for (int j = 0; j < 2; ++j) {
            float ii = fast_sig(acc[j][0]);
            float ff = fast_sig(acc[j][1]);
            float gg = fast_tanh(acc[j][2]);
            float oo = fast_sig(acc[j][3]);
            float cn = fmaf(ff, c[j], ii * gg);
            c[j] = cn;
            hn[j] = oo * fast_tanh(cn);
        }

        // ---- fill next buffer: x_{t+1} + h_t ----
        float* nv = &v[1 - p][0][0];
        if (DIN == 128) {
            if (havex)
                *reinterpret_cast<float2*>(nv + (size_t)xb * KP + xk) = xr;
        } else {
            if (havex && tid < 8 * DIN)
                nv[(size_t)xb * KP + xk] = xr.x;
        }
#pragma unroll
        for (int j = 0; j < 2; ++j)
            nv[(size_t)(grp * 2 + j) * KP + DIN + u] = hn[j];

        if (hout) {
#pragma unroll
            for (int j = 0; j < 2; ++j)
                hout[((size_t)(bb + j) * NT + t) * NH + u] = hn[j];
        }
        if (hlast && t == NT - 1) {
#pragma unroll
            for (int j = 0; j < 2; ++j)
                hlast[(bb + j) * NH + u] = hn[j];
        }

        __syncthreads();
        p ^= 1;
    }
}

// ---------------- final FC on last timestep of layer 2 ----------------
__global__ void fc_kernel(const float* __restrict__ fc_w,
                          const float* __restrict__ fc_b,
                          float* __restrict__ out)
{
    int b = blockIdx.x;
    int tid = threadIdx.x;           // 128 threads, one per unit
    float p = g_hlast[b * NH + tid] * fc_w[tid];
#pragma unroll
    for (int o = 16; o; o >>= 1) p += __shfl_down_sync(0xffffffffu, p, o);
    __shared__ float ws[4];
    if ((tid & 31) == 0) ws[tid >> 5] = p;
    __syncthreads();
    if (tid == 0) out[b] = ws[0] + ws[1] + ws[2] + ws[3] + fc_b[0];
}

// ---------------- launch ----------------
extern "C" void kernel_launch(void* const* d_in, const int* in_sizes, int n_in,
                              void* d_out, int out_size)
{
    const float* x    = (const float*)d_in[0];
    const float* wih0 = (const float*)d_in[1];
    const float* whh0 = (const float*)d_in[2];
    const float* bih0 = (const float*)d_in[3];
    const float* bhh0 = (const float*)d_in[4];
    const float* wih1 = (const float*)d_in[5];
    const float* whh1 = (const float*)d_in[6];
    const float* bih1 = (const float*)d_in[7];
    const float* bhh1 = (const float*)d_in[8];
    const float* wih2 = (const float*)d_in[9];
    const float* whh2 = (const float*)d_in[10];
    const float* bih2 = (const float*)d_in[11];
    const float* bhh2 = (const float*)d_in[12];
    const float* fcw  = (const float*)d_in[13];
    const float* fcb  = (const float*)d_in[14];
    float* out = (float*)d_out;

    void *ph0 = nullptr, *ph1 = nullptr, *phl = nullptr;
    cudaGetSymbolAddress(&ph0, g_h0);
    cudaGetSymbolAddress(&ph1, g_h1);
    cudaGetSymbolAddress(&phl, g_hlast);

    prep_kernel<<<132, 256>>>(wih0, whh0, bih0, bhh0, 0, 6,   136);
    prep_kernel<<<132, 256>>>(wih1, whh1, bih1, bhh1, 1, 128, 256);
    prep_kernel<<<132, 256>>>(wih2, whh2, bih2, bhh2, 2, 128, 256);

    lstm_layer_kernel<6>  <<<NB / 8, 512>>>(x, (float*)ph0, nullptr, 0);
    lstm_layer_kernel<128><<<NB / 8, 512>>>((const float*)ph0, (float*)ph1, nullptr, 1);
    lstm_layer_kernel<128><<<NB / 8, 512>>>((const float*)ph1, nullptr, (float*)phl, 2);

    fc_kernel<<<NB, 128>>>(fcw, fcb, out);
}

// round 4
// speedup vs baseline: 2.2746x; 1.6737x over previous
#include <cuda_runtime.h>
#include <cstdint>
#include <cstddef>

#define NB 1024
#define NT 512
#define NH 128
#define NG 512   // 4*H

// ---------------- scratch (device globals; no runtime allocation) ----------------
__device__ float g_h0[(size_t)NB * NT * NH];   // layer0 output  [B][T][H]
__device__ float g_h1[(size_t)NB * NT * NH];   // layer1 output  [B][T][H]
__device__ float g_hlast[NB * NH];             // layer2 last-step h
__device__ float g_WT[3][256 * NG];            // per layer: [k][u][4] (i,f,g,o packed)
__device__ float g_bias[3][NG];                // per layer: [u][4]

// ---------------- weight transpose / pack ----------------
// WT[k][u][q] = (k < din) ? w_ih[q*H+u][k] : w_hh[q*H+u][k-din];  zeros for k >= din+H
__global__ void prep_kernel(const float* __restrict__ w_ih, const float* __restrict__ w_hh,
                            const float* __restrict__ b_ih, const float* __restrict__ b_hh,
                            int layer, int din, int kp)
{
    float* WT = g_WT[layer];
    int total = kp * NG;
    for (int idx = blockIdx.x * blockDim.x + threadIdx.x; idx < total;
         idx += gridDim.x * blockDim.x) {
        int q = idx & 3;
        int u = (idx >> 2) & (NH - 1);
        int k = idx >> 9;
        int g = q * NH + u;
        float val = 0.0f;
        if (k < din)            val = w_ih[g * din + k];
        else if (k < din + NH)  val = w_hh[g * NH + (k - din)];
        WT[idx] = val;
    }
    for (int g = blockIdx.x * blockDim.x + threadIdx.x; g < NG;
         g += gridDim.x * blockDim.x) {
        int q = g / NH, u = g % NH;
        g_bias[layer][u * 4 + q] = b_ih[g] + b_hh[g];
    }
}

// ---------------- activations (HW MUFU.TANH) ----------------
__device__ __forceinline__ float fast_tanh(float x) {
    float y;
    asm("tanh.approx.f32 %0, %1;" : "=f"(y) : "f"(x));
    return y;
}
__device__ __forceinline__ float fast_sig(float x) {
    return fmaf(0.5f, fast_tanh(0.5f * x), 0.5f);
}

#define ACC4(j, xv)                                                                     \
    acc[j][0] = fmaf(w0.x, xv.x, fmaf(w1.x, xv.y, fmaf(w2.x, xv.z, fmaf(w3.x, xv.w, acc[j][0])))); \
    acc[j][1] = fmaf(w0.y, xv.x, fmaf(w1.y, xv.y, fmaf(w2.y, xv.z, fmaf(w3.y, xv.w, acc[j][1])))); \
    acc[j][2] = fmaf(w0.z, xv.x, fmaf(w1.z, xv.y, fmaf(w2.z, xv.z, fmaf(w3.z, xv.w, acc[j][2])))); \
    acc[j][3] = fmaf(w0.w, xv.x, fmaf(w1.w, xv.y, fmaf(w2.w, xv.z, fmaf(w3.w, xv.w, acc[j][3]))));

// ---------------- LSTM layer ----------------
// One CTA = 8 batch rows, 512 threads = 128 units x 4 K-GROUPS (disjoint K ranges:
// weight duplication = 1). Thread FFMA tile = 4 gates x 8 batches x KP/4 k's.
// Cross-group reduction via smem partials; bias folded into group 0.
// Double-buffered v; 2 syncthreads per step.
template <int DIN>
__global__ void __launch_bounds__(512, 1)
lstm_layer_kernel(const float* __restrict__ xin,  // [B][T][DIN]
                  float* __restrict__ hout,       // [B][T][H] or nullptr
                  float* __restrict__ hlast,      // [B][H]   or nullptr
                  int layer)
{
    constexpr int K  = DIN + NH;
    constexpr int KP = (K + 15) & ~15;    // 144 (layer0) / 256 (layers 1,2)
    constexpr int KG = KP / 4;            // 36 / 64 per k-group

    extern __shared__ __align__(16) char smem_dyn[];
    float* v = reinterpret_cast<float*>(smem_dyn);                 // [2][8][KP]
    float4* part = reinterpret_cast<float4*>(smem_dyn + 2 * 8 * KP * sizeof(float)); // [8][4][128]

    const float4* __restrict__ WT4 = reinterpret_cast<const float4*>(g_WT[layer]);

    const int tid = threadIdx.x;
    const int u   = tid & (NH - 1);
    const int kg  = tid >> 7;             // 0..3
    const int b0  = blockIdx.x * 8;
    const int kbase = kg * KG;

    const float4 bias4 = *reinterpret_cast<const float4*>(&g_bias[layer][u * 4]);

    // zero both v buffers (h regions + pads must start at 0)
    for (int i = tid; i < 2 * 8 * KP; i += 512) v[i] = 0.0f;

    // stage x_0 into buffer 0
    if (DIN == 128) {
        int b = tid >> 6, k2 = (tid & 63) * 2;
        *reinterpret_cast<float2*>(&v[(size_t)b * KP + k2]) =
            *reinterpret_cast<const float2*>(&xin[((size_t)(b0 + b) * NT + 0) * DIN + k2]);
    } else {
        if (tid < 8 * DIN) {
            int b = tid / DIN, k = tid - b * DIN;
            v[(size_t)b * KP + k] = xin[((size_t)(b0 + b) * NT + 0) * DIN + k];
        }
    }
    __syncthreads();

    // this thread finalizes cells (kg, u) and (kg+4, u); c state lives here
    float cst[2] = {0.f, 0.f};
    int p = 0;

    for (int t = 0; t < NT; ++t) {
        // ---- prefetch x_{t+1} into registers (overlaps FFMA block) ----
        float2 xr = {0.f, 0.f};
        const bool havex = (t + 1 < NT);
        int xb = 0, xk = 0;
        if (DIN == 128) {
            xb = tid >> 6; xk = (tid & 63) * 2;
            if (havex)
                xr = *reinterpret_cast<const float2*>(
                    &xin[((size_t)(b0 + xb) * NT + (t + 1)) * DIN + xk]);
        } else {
            if (havex && tid < 8 * DIN) {
                xb = tid / DIN; xk = tid - xb * DIN;
                xr.x = xin[((size_t)(b0 + xb) * NT + (t + 1)) * DIN + xk];
            }
        }

        // ---- partial gates over this group's K range, all 8 batches ----
        float acc[8][4];
        if (kg == 0) {
#pragma unroll
            for (int j = 0; j < 8; ++j) {
                acc[j][0] = bias4.x; acc[j][1] = bias4.y;
                acc[j][2] = bias4.z; acc[j][3] = bias4.w;
            }
        } else {
#pragma unroll
            for (int j = 0; j < 8; ++j)
                acc[j][0] = acc[j][1] = acc[j][2] = acc[j][3] = 0.f;
        }

        const float* vp = v + (size_t)p * 8 * KP;

#pragma unroll 2
        for (int kk = 0; kk < KG; kk += 4) {
            const int k = kbase + kk;
            float4 w0 = WT4[(size_t)(k + 0) * NH + u];
            float4 w1 = WT4[(size_t)(k + 1) * NH + u];
            float4 w2 = WT4[(size_t)(k + 2) * NH + u];
            float4 w3 = WT4[(size_t)(k + 3) * NH + u];
#pragma unroll
            for (int j = 0; j < 8; ++j) {
                float4 xv = *reinterpret_cast<const float4*>(vp + (size_t)j * KP + k);
                ACC4(j, xv)
            }
        }

        // ---- write partials: part[b][kg][u] ----
#pragma unroll
        for (int j = 0; j < 8; ++j)
            part[((size_t)j * 4 + kg) * NH + u] =
                make_float4(acc[j][0], acc[j][1], acc[j][2], acc[j][3]);
        __syncthreads();

        // ---- reduce + pointwise for 2 cells: batches kg and kg+4 ----
        float* nv = v + (size_t)(1 - p) * 8 * KP;
#pragma unroll
        for (int cell = 0; cell < 2; ++cell) {
            const int j = kg + cell * 4;
            float4 s0 = part[((size_t)j * 4 + 0) * NH + u];
            float4 s1 = part[((size_t)j * 4 + 1) * NH + u];
            float4 s2 = part[((size_t)j * 4 + 2) * NH + u];
            float4 s3 = part[((size_t)j * 4 + 3) * NH + u];
            float gi = (s0.x + s1.x) + (s2.x + s3.x);
            float gf = (s0.y + s1.y) + (s2.y + s3.y);
            float gg = (s0.z + s1.z) + (s2.z + s3.z);
            float go = (s0.w + s1.w) + (s2.w + s3.w);
            float ii = fast_sig(gi);
            float ff = fast_sig(gf);
            float g2 = fast_tanh(gg);
            float oo = fast_sig(go);
            float cn = fmaf(ff, cst[cell], ii * g2);
            cst[cell] = cn;
            float hn = oo * fast_tanh(cn);

            nv[(size_t)j * KP + DIN + u] = hn;
            if (hout)
                hout[((size_t)(b0 + j) * NT + t) * NH + u] = hn;
            if (hlast && t == NT - 1)
                hlast[(b0 + j) * NH + u] = hn;
        }

        // ---- write prefetched x_{t+1} into next buffer ----
        if (DIN == 128) {
            if (havex)
                *reinterpret_cast<float2*>(nv + (size_t)xb * KP + xk) = xr;
        } else {
            if (havex && tid < 8 * DIN)
                nv[(size_t)xb * KP + xk] = xr.x;
        }

        __syncthreads();
        p ^= 1;
    }
}

// ---------------- final FC on last timestep of layer 2 ----------------
__global__ void fc_kernel(const float* __restrict__ fc_w,
                          const float* __restrict__ fc_b,
                          float* __restrict__ out)
{
    int b = blockIdx.x;
    int tid = threadIdx.x;           // 128 threads, one per unit
    float p = g_hlast[b * NH + tid] * fc_w[tid];
#pragma unroll
    for (int o = 16; o; o >>= 1) p += __shfl_down_sync(0xffffffffu, p, o);
    __shared__ float ws[4];
    if ((tid & 31) == 0) ws[tid >> 5] = p;
    __syncthreads();
    if (tid == 0) out[b] = ws[0] + ws[1] + ws[2] + ws[3] + fc_b[0];
}

// ---------------- launch ----------------
extern "C" void kernel_launch(void* const* d_in, const int* in_sizes, int n_in,
                              void* d_out, int out_size)
{
    const float* x    = (const float*)d_in[0];
    const float* wih0 = (const float*)d_in[1];
    const float* whh0 = (const float*)d_in[2];
    const float* bih0 = (const float*)d_in[3];
    const float* bhh0 = (const float*)d_in[4];
    const float* wih1 = (const float*)d_in[5];
    const float* whh1 = (const float*)d_in[6];
    const float* bih1 = (const float*)d_in[7];
    const float* bhh1 = (const float*)d_in[8];
    const float* wih2 = (const float*)d_in[9];
    const float* whh2 = (const float*)d_in[10];
    const float* bih2 = (const float*)d_in[11];
    const float* bhh2 = (const float*)d_in[12];
    const float* fcw  = (const float*)d_in[13];
    const float* fcb  = (const float*)d_in[14];
    float* out = (float*)d_out;

    void *ph0 = nullptr, *ph1 = nullptr, *phl = nullptr;
    cudaGetSymbolAddress(&ph0, g_h0);
    cudaGetSymbolAddress(&ph1, g_h1);
    cudaGetSymbolAddress(&phl, g_hlast);

    // dynamic smem: v[2][8][KP] + part[8][4][128] float4
    const int smem0 = 2 * 8 * 144 * 4 + 8 * 4 * 128 * 16;   // 9216 + 65536
    const int smem1 = 2 * 8 * 256 * 4 + 8 * 4 * 128 * 16;   // 16384 + 65536
    cudaFuncSetAttribute(lstm_layer_kernel<6>,
                         cudaFuncAttributeMaxDynamicSharedMemorySize, smem0);
    cudaFuncSetAttribute(lstm_layer_kernel<128>,
                         cudaFuncAttributeMaxDynamicSharedMemorySize, smem1);

    prep_kernel<<<132, 256>>>(wih0, whh0, bih0, bhh0, 0, 6,   144);
    prep_kernel<<<132, 256>>>(wih1, whh1, bih1, bhh1, 1, 128, 256);
    prep_kernel<<<132, 256>>>(wih2, whh2, bih2, bhh2, 2, 128, 256);

    lstm_layer_kernel<6>  <<<NB / 8, 512, smem0>>>(x, (float*)ph0, nullptr, 0);
    lstm_layer_kernel<128><<<NB / 8, 512, smem1>>>((const float*)ph0, (float*)ph1, nullptr, 1);
    lstm_layer_kernel<128><<<NB / 8, 512, smem1>>>((const float*)ph1, nullptr, (float*)phl, 2);

    fc_kernel<<<NB, 128>>>(fcw, fcb, out);
}

// round 5
// speedup vs baseline: 2.3019x; 1.0120x over previous
#include <cuda_runtime.h>
#include <cuda_fp16.h>
#include <cstdint>
#include <cstddef>

#define NB 1024
#define NT 512
#define NH 128
#define NG 512   // 4*H

// ---------------- scratch (device globals; no runtime allocation) ----------------
__device__ __half g_h0[(size_t)NB * NT * NH];  // layer0 output (fp16) [B][T][H]
__device__ __half g_h1[(size_t)NB * NT * NH];  // layer1 output (fp16) [B][T][H]
__device__ float  g_hlast[NB * NH];            // layer2 last-step h (fp32)
// fp16 packed weights: per (kk,u): 8 halves = [g0(k=2kk),g0(2kk+1),g1...,g3...] = 16B
__device__ __half g_WTh[3][256 * NG];          // 256 kk max * 128 u * 8 halves
__device__ float  g_bias[3][NG];               // [u][4] gate order i,f,g,o

// ---------------- weight transpose / pack (fp16) ----------------
__global__ void prep_kernel(const float* __restrict__ w_ih, const float* __restrict__ w_hh,
                            const float* __restrict__ b_ih, const float* __restrict__ b_hh,
                            int layer, int din, int kp)
{
    __half* WT = g_WTh[layer];
    int total = kp * NG;   // kp/2 kk * 128 u * 8 halves
    for (int idx = blockIdx.x * blockDim.x + threadIdx.x; idx < total;
         idx += gridDim.x * blockDim.x) {
        int h8  = idx & 7;
        int q   = h8 >> 1;
        int par = h8 & 1;
        int u   = (idx >> 3) & (NH - 1);
        int kk  = idx >> 10;
        int k   = 2 * kk + par;
        int g   = q * NH + u;
        float val = 0.0f;
        if (k < din)            val = w_ih[g * din + k];
        else if (k < din + NH)  val = w_hh[g * NH + (k - din)];
        WT[idx] = __float2half(val);
    }
    for (int g = blockIdx.x * blockDim.x + threadIdx.x; g < NG;
         g += gridDim.x * blockDim.x) {
        int q = g / NH, u = g % NH;
        g_bias[layer][u * 4 + q] = b_ih[g] + b_hh[g];
    }
}

// ---------------- activations (HW MUFU.TANH) ----------------
__device__ __forceinline__ float fast_tanh(float x) {
    float y;
    asm("tanh.approx.f32 %0, %1;" : "=f"(y) : "f"(x));
    return y;
}
__device__ __forceinline__ float fast_sig(float x) {
    return fmaf(0.5f, fast_tanh(0.5f * x), 0.5f);
}

// ---------------- LSTM layer (fp16 HFMA2 math, fp32 windowed accumulate) --------
// One CTA = 8 batch rows, 512 threads = 128 units x 4 K-groups (disjoint K).
// Per 4-kk block: 4 LDG.128 (weights) + 8 LDS.128 (x per batch) + 128 HFMA2.
// fp16 window = 8 kk (16 k) -> flush to fp32 acc. Cross-group reduce via smem.
template <int DIN, int KP>
__global__ void __launch_bounds__(512, 1)
lstm_layer_kernel(const void* __restrict__ xin_v,  // fp32 [B][T][DIN] or fp16 [B][T][128]
                  __half* __restrict__ hout,       // fp16 [B][T][H] or nullptr
                  float* __restrict__ hlast,       // fp32 [B][H]   or nullptr
                  int layer)
{
    constexpr int KK   = KP / 2;    // half2 per row
    constexpr int KG2  = KP / 8;    // kk per k-group (20 / 32)
    constexpr int NBLK = KG2 / 4;   // 4-kk blocks per group (5 / 8)

    extern __shared__ __align__(16) char smem_dyn[];
    __half* v = reinterpret_cast<__half*>(smem_dyn);                        // [2][8][KP]
    float4* part = reinterpret_cast<float4*>(smem_dyn + 2 * 8 * KP * 2);    // [8][4][128]

    const uint4* __restrict__ WTH = reinterpret_cast<const uint4*>(g_WTh[layer]);

    const int tid = threadIdx.x;
    const int u   = tid & (NH - 1);
    const int kg  = tid >> 7;             // 0..3
    const int b0  = blockIdx.x * 8;
    const int kb0 = kg * KG2;             // group base (kk units)

    const float4 bias4 = *reinterpret_cast<const float4*>(&g_bias[layer][u * 4]);

    // zero both v buffers (h region + pads must start at 0)
    for (int i = tid; i < 2 * 8 * KK; i += 512)
        reinterpret_cast<uint32_t*>(v)[i] = 0u;
    __syncthreads();

    // stage x_0 into buffer 0
    if (DIN == 128) {
        const __half* xin = (const __half*)xin_v;
        int b = tid >> 6, k2 = tid & 63;
        reinterpret_cast<__half2*>(v)[(size_t)b * KK + k2] =
            reinterpret_cast<const __half2*>(&xin[((size_t)(b0 + b) * NT + 0) * 128])[k2];
    } else {
        const float* xin = (const float*)xin_v;
        if (tid < 8 * DIN) {
            int b = tid / DIN, k = tid - b * DIN;
            v[(size_t)b * KP + k] = __float2half(xin[((size_t)(b0 + b) * NT + 0) * DIN + k]);
        }
    }
    __syncthreads();

    float cst[2] = {0.f, 0.f};
    int p = 0;

    for (int t = 0; t < NT; ++t) {
        // ---- prefetch x_{t+1} (overlaps math) ----
        const bool havex = (t + 1 < NT);
        __half2 xrh = __float2half2_rn(0.f);
        float   xrf = 0.f;
        int xb = 0, xk = 0;
        if (DIN == 128) {
            const __half* xin = (const __half*)xin_v;
            xb = tid >> 6; xk = tid & 63;
            if (havex)
                xrh = reinterpret_cast<const __half2*>(
                    &xin[((size_t)(b0 + xb) * NT + (t + 1)) * 128])[xk];
        } else {
            const float* xin = (const float*)xin_v;
            if (havex && tid < 8 * DIN) {
                xb = tid / DIN; xk = tid - xb * DIN;
                xrf = xin[((size_t)(b0 + xb) * NT + (t + 1)) * DIN + xk];
            }
        }

        // ---- partial gates over this group's K range, all 8 batches ----
        float acc[8][4];
        if (kg == 0) {
#pragma unroll
            for (int j = 0; j < 8; ++j) {
                acc[j][0] = bias4.x; acc[j][1] = bias4.y;
                acc[j][2] = bias4.z; acc[j][3] = bias4.w;
            }
        } else {
#pragma unroll
            for (int j = 0; j < 8; ++j)
                acc[j][0] = acc[j][1] = acc[j][2] = acc[j][3] = 0.f;
        }

        __half2 acch[8][4];
#pragma unroll
        for (int j = 0; j < 8; ++j)
#pragma unroll
            for (int q = 0; q < 4; ++q) acch[j][q] = __float2half2_rn(0.f);

        const __half* vp = v + (size_t)p * 8 * KP;

#pragma unroll
        for (int blk = 0; blk < NBLK; ++blk) {
            const int kkb = kb0 + blk * 4;
            uint4 wv0 = WTH[(size_t)(kkb + 0) * NH + u];
            uint4 wv1 = WTH[(size_t)(kkb + 1) * NH + u];
            uint4 wv2 = WTH[(size_t)(kkb + 2) * NH + u];
            uint4 wv3 = WTH[(size_t)(kkb + 3) * NH + u];
            const __half2* w0 = reinterpret_cast<const __half2*>(&wv0);
            const __half2* w1 = reinterpret_cast<const __half2*>(&wv1);
            const __half2* w2 = reinterpret_cast<const __half2*>(&wv2);
            const __half2* w3 = reinterpret_cast<const __half2*>(&wv3);
#pragma unroll
            for (int j = 0; j < 8; ++j) {
                uint4 xv = *reinterpret_cast<const uint4*>(vp + (size_t)j * KP + 2 * kkb);
                const __half2* xp = reinterpret_cast<const __half2*>(&xv);
#pragma unroll
                for (int q = 0; q < 4; ++q) {
                    acch[j][q] = __hfma2(w0[q], xp[0], acch[j][q]);
                    acch[j][q] = __hfma2(w1[q], xp[1], acch[j][q]);
                    acch[j][q] = __hfma2(w2[q], xp[2], acch[j][q]);
                    acch[j][q] = __hfma2(w3[q], xp[3], acch[j][q]);
                }
            }
            // flush fp16 window (every 8 kk = 16 k, and at group end)
            if ((blk & 1) || blk == NBLK - 1) {
#pragma unroll
                for (int j = 0; j < 8; ++j)
#pragma unroll
                    for (int q = 0; q < 4; ++q) {
                        float2 f = __half22float2(acch[j][q]);
                        acc[j][q] += f.x;
                        acc[j][q] += f.y;
                        acch[j][q] = __float2half2_rn(0.f);
                    }
            }
        }

        // ---- write partials: part[b][kg][u] ----
#pragma unroll
        for (int j = 0; j < 8; ++j)
            part[((size_t)j * 4 + kg) * NH + u] =
                make_float4(acc[j][0], acc[j][1], acc[j][2], acc[j][3]);
        __syncthreads();

        // ---- reduce + pointwise for 2 cells: batches kg and kg+4 ----
        __half* nv = v + (size_t)(1 - p) * 8 * KP;
#pragma unroll
        for (int cell = 0; cell < 2; ++cell) {
            const int j = kg + cell * 4;
            float4 s0 = part[((size_t)j * 4 + 0) * NH + u];
            float4 s1 = part[((size_t)j * 4 + 1) * NH + u];
            float4 s2 = part[((size_t)j * 4 + 2) * NH + u];
            float4 s3 = part[((size_t)j * 4 + 3) * NH + u];
            float gi = (s0.x + s1.x) + (s2.x + s3.x);
            float gf = (s0.y + s1.y) + (s2.y + s3.y);
            float gg = (s0.z + s1.z) + (s2.z + s3.z);
            float go = (s0.w + s1.w) + (s2.w + s3.w);
            float ii = fast_sig(gi);
            float ff = fast_sig(gf);
            float g2 = fast_tanh(gg);
            float oo = fast_sig(go);
            float cn = fmaf(ff, cst[cell], ii * g2);
            cst[cell] = cn;
            float hn = oo * fast_tanh(cn);

            nv[(size_t)j * KP + DIN + u] = __float2half(hn);
            if (hout)
                hout[((size_t)(b0 + j) * NT + t) * NH + u] = __float2half(hn);
            if (hlast && t == NT - 1)
                hlast[(b0 + j) * NH + u] = hn;
        }

        // ---- write prefetched x_{t+1} into next buffer ----
        if (DIN == 128) {
            if (havex)
                reinterpret_cast<__half2*>(nv)[(size_t)xb * KK + xk] = xrh;
        } else {
            if (havex && tid < 8 * DIN)
                nv[(size_t)xb * KP + xk] = __float2half(xrf);
        }

        __syncthreads();
        p ^= 1;
    }
}

// ---------------- final FC on last timestep of layer 2 ----------------
__global__ void fc_kernel(const float* __restrict__ fc_w,
                          const float* __restrict__ fc_b,
                          float* __restrict__ out)
{
    int b = blockIdx.x;
    int tid = threadIdx.x;           // 128 threads, one per unit
    float p = g_hlast[b * NH + tid] * fc_w[tid];
#pragma unroll
    for (int o = 16; o; o >>= 1) p += __shfl_down_sync(0xffffffffu, p, o);
    __shared__ float ws[4];
    if ((tid & 31) == 0) ws[tid >> 5] = p;
    __syncthreads();
    if (tid == 0) out[b] = ws[0] + ws[1] + ws[2] + ws[3] + fc_b[0];
}

// ---------------- launch ----------------
extern "C" void kernel_launch(void* const* d_in, const int* in_sizes, int n_in,
                              void* d_out, int out_size)
{
    const float* x    = (const float*)d_in[0];
    const float* wih0 = (const float*)d_in[1];
    const float* whh0 = (const float*)d_in[2];
    const float* bih0 = (const float*)d_in[3];
    const float* bhh0 = (const float*)d_in[4];
    const float* wih1 = (const float*)d_in[5];
    const float* whh1 = (const float*)d_in[6];
    const float* bih1 = (const float*)d_in[7];
    const float* bhh1 = (const float*)d_in[8];
    const float* wih2 = (const float*)d_in[9];
    const float* whh2 = (const float*)d_in[10];
    const float* bih2 = (const float*)d_in[11];
    const float* bhh2 = (const float*)d_in[12];
    const float* fcw  = (const float*)d_in[13];
    const float* fcb  = (const float*)d_in[14];
    float* out = (float*)d_out;

    void *ph0 = nullptr, *ph1 = nullptr, *phl = nullptr;
    cudaGetSymbolAddress(&ph0, g_h0);
    cudaGetSymbolAddress(&ph1, g_h1);
    cudaGetSymbolAddress(&phl, g_hlast);

    // dynamic smem: v[2][8][KP] halves + part[8][4][128] float4
    const int smem0 = 2 * 8 * 160 * 2 + 8 * 4 * 128 * 16;   // 5120 + 65536
    const int smem1 = 2 * 8 * 256 * 2 + 8 * 4 * 128 * 16;   // 8192 + 65536
    cudaFuncSetAttribute((const void*)lstm_layer_kernel<6, 160>,
                         cudaFuncAttributeMaxDynamicSharedMemorySize, smem0);
    cudaFuncSetAttribute((const void*)lstm_layer_kernel<128, 256>,
                         cudaFuncAttributeMaxDynamicSharedMemorySize, smem1);

    prep_kernel<<<132, 256>>>(wih0, whh0, bih0, bhh0, 0, 6,   160);
    prep_kernel<<<132, 256>>>(wih1, whh1, bih1, bhh1, 1, 128, 256);
    prep_kernel<<<132, 256>>>(wih2, whh2, bih2, bhh2, 2, 128, 256);

    lstm_layer_kernel<6, 160>  <<<NB / 8, 512, smem0>>>(x, (__half*)ph0, nullptr, 0);
    lstm_layer_kernel<128, 256><<<NB / 8, 512, smem1>>>(ph0, (__half*)ph1, nullptr, 1);
    lstm_layer_kernel<128, 256><<<NB / 8, 512, smem1>>>(ph1, nullptr, (float*)phl, 2);

    fc_kernel<<<NB, 128>>>(fcw, fcb, out);
}

// round 6
// speedup vs baseline: 2.8118x; 1.2215x over previous
#include <cuda_runtime.h>
#include <cuda_fp16.h>
#include <cstdint>
#include <cstddef>

#define NB 1024
#define NT 512
#define NH 128
#define NG 512   // 4*H

// ---------------- scratch (device globals; no runtime allocation) ----------------
__device__ __half g_h0[(size_t)NB * NT * NH];  // layer0 output (fp16) [B][T][H]
__device__ __half g_h1[(size_t)NB * NT * NH];  // layer1 output (fp16) [B][T][H]
__device__ float  g_hlast[NB * NH];            // layer2 last-step h (fp32)
// fp16 packed weights: per (kk,u): 8 halves = [g0(k=2kk),g0(2kk+1),g1...,g3...] = 16B
__device__ __half g_WTh[3][256 * NG];          // 256 kk max * 128 u * 8 halves
__device__ float  g_bias[3][NG];               // [u][4] gate order i,f,g,o

// ---------------- weight transpose / pack (fp16) ----------------
__global__ void prep_kernel(const float* __restrict__ w_ih, const float* __restrict__ w_hh,
                            const float* __restrict__ b_ih, const float* __restrict__ b_hh,
                            int layer, int din, int kp)
{
    __half* WT = g_WTh[layer];
    int total = kp * NG;   // kp/2 kk * 128 u * 8 halves
    for (int idx = blockIdx.x * blockDim.x + threadIdx.x; idx < total;
         idx += gridDim.x * blockDim.x) {
        int h8  = idx & 7;
        int q   = h8 >> 1;
        int par = h8 & 1;
        int u   = (idx >> 3) & (NH - 1);
        int kk  = idx >> 10;
        int k   = 2 * kk + par;
        int g   = q * NH + u;
        float val = 0.0f;
        if (k < din)            val = w_ih[g * din + k];
        else if (k < din + NH)  val = w_hh[g * NH + (k - din)];
        WT[idx] = __float2half(val);
    }
    for (int g = blockIdx.x * blockDim.x + threadIdx.x; g < NG;
         g += gridDim.x * blockDim.x) {
        int q = g / NH, u = g % NH;
        g_bias[layer][u * 4 + q] = b_ih[g] + b_hh[g];
    }
}

// ---------------- activations (HW MUFU.TANH) ----------------
__device__ __forceinline__ float fast_tanh(float x) {
    float y;
    asm("tanh.approx.f32 %0, %1;" : "=f"(y) : "f"(x));
    return y;
}
__device__ __forceinline__ float fast_sig(float x) {
    return fmaf(0.5f, fast_tanh(0.5f * x), 0.5f);
}

// ---------------- LSTM layer (fp16 HFMA2 math, single end-of-group convert) -----
// One CTA = 8 batch rows, 512 threads = 128 units x 4 K-groups (disjoint K).
// Inner loop: pure LDG.128 (weights) + LDS.128 (x) + HFMA2, fp16 accumulators
// held across the whole group K-range; ONE fp32 conversion per step at the
// partial write (bias folded in). Cross-group reduce via smem partials.
template <int DIN, int KP>
__global__ void __launch_bounds__(512, 1)
lstm_layer_kernel(const void* __restrict__ xin_v,  // fp32 [B][T][DIN] or fp16 [B][T][128]
                  __half* __restrict__ hout,       // fp16 [B][T][H] or nullptr
                  float* __restrict__ hlast,       // fp32 [B][H]   or nullptr
                  int layer)
{
    constexpr int KK   = KP / 2;    // half2 per row
    constexpr int KG2  = KP / 8;    // kk per k-group (20 / 32)
    constexpr int NBLK = KG2 / 4;   // 4-kk blocks per group (5 / 8)

    extern __shared__ __align__(16) char smem_dyn[];
    __half* v = reinterpret_cast<__half*>(smem_dyn);                        // [2][8][KP]
    float4* part = reinterpret_cast<float4*>(smem_dyn + 2 * 8 * KP * 2);    // [8][4][128]

    const uint4* __restrict__ WTH = reinterpret_cast<const uint4*>(g_WTh[layer]);

    const int tid = threadIdx.x;
    const int u   = tid & (NH - 1);
    const int kg  = tid >> 7;             // 0..3
    const int b0  = blockIdx.x * 8;
    const int kb0 = kg * KG2;             // group base (kk units)

    const float4 bias4 = *reinterpret_cast<const float4*>(&g_bias[layer][u * 4]);

    // zero both v buffers (h region + pads must start at 0)
    for (int i = tid; i < 2 * 8 * KK; i += 512)
        reinterpret_cast<uint32_t*>(v)[i] = 0u;
    __syncthreads();

    // stage x_0 into buffer 0
    if (DIN == 128) {
        const __half* xin = (const __half*)xin_v;
        int b = tid >> 6, k2 = tid & 63;
        reinterpret_cast<__half2*>(v)[(size_t)b * KK + k2] =
            reinterpret_cast<const __half2*>(&xin[((size_t)(b0 + b) * NT + 0) * 128])[k2];
    } else {
        const float* xin = (const float*)xin_v;
        if (tid < 8 * DIN) {
            int b = tid / DIN, k = tid - b * DIN;
            v[(size_t)b * KP + k] = __float2half(xin[((size_t)(b0 + b) * NT + 0) * DIN + k]);
        }
    }
    __syncthreads();

    float cst[2] = {0.f, 0.f};
    int p = 0;

    for (int t = 0; t < NT; ++t) {
        // ---- prefetch x_{t+1} (overlaps math) ----
        const bool havex = (t + 1 < NT);
        __half2 xrh = __float2half2_rn(0.f);
        float   xrf = 0.f;
        int xb = 0, xk = 0;
        if (DIN == 128) {
            const __half* xin = (const __half*)xin_v;
            xb = tid >> 6; xk = tid & 63;
            if (havex)
                xrh = reinterpret_cast<const __half2*>(
                    &xin[((size_t)(b0 + xb) * NT + (t + 1)) * 128])[xk];
        } else {
            const float* xin = (const float*)xin_v;
            if (havex && tid < 8 * DIN) {
                xb = tid / DIN; xk = tid - xb * DIN;
                xrf = xin[((size_t)(b0 + xb) * NT + (t + 1)) * DIN + xk];
            }
        }

        // ---- fp16 partial gates over this group's K range, all 8 batches ----
        __half2 acch[8][4];
#pragma unroll
        for (int j = 0; j < 8; ++j)
#pragma unroll
            for (int q = 0; q < 4; ++q) acch[j][q] = __float2half2_rn(0.f);

        const __half* vp = v + (size_t)p * 8 * KP;

#pragma unroll
        for (int blk = 0; blk < NBLK; ++blk) {
            const int kkb = kb0 + blk * 4;
            uint4 wv0 = WTH[(size_t)(kkb + 0) * NH + u];
            uint4 wv1 = WTH[(size_t)(kkb + 1) * NH + u];
            uint4 wv2 = WTH[(size_t)(kkb + 2) * NH + u];
            uint4 wv3 = WTH[(size_t)(kkb + 3) * NH + u];
            const __half2* w0 = reinterpret_cast<const __half2*>(&wv0);
            const __half2* w1 = reinterpret_cast<const __half2*>(&wv1);
            const __half2* w2 = reinterpret_cast<const __half2*>(&wv2);
            const __half2* w3 = reinterpret_cast<const __half2*>(&wv3);
#pragma unroll
            for (int j = 0; j < 8; ++j) {
                uint4 xv = *reinterpret_cast<const uint4*>(vp + (size_t)j * KP + 2 * kkb);
                const __half2* xp = reinterpret_cast<const __half2*>(&xv);
#pragma unroll
                for (int q = 0; q < 4; ++q) {
                    acch[j][q] = __hfma2(w0[q], xp[0], acch[j][q]);
                    acch[j][q] = __hfma2(w1[q], xp[1], acch[j][q]);
                    acch[j][q] = __hfma2(w2[q], xp[2], acch[j][q]);
                    acch[j][q] = __hfma2(w3[q], xp[3], acch[j][q]);
                }
            }
        }

        // ---- single conversion + partial write: part[b][kg][u] (bias in kg 0) ----
#pragma unroll
        for (int j = 0; j < 8; ++j) {
            float4 pr;
            pr.x = __low2float(acch[j][0]) + __high2float(acch[j][0]);
            pr.y = __low2float(acch[j][1]) + __high2float(acch[j][1]);
            pr.z = __low2float(acch[j][2]) + __high2float(acch[j][2]);
            pr.w = __low2float(acch[j][3]) + __high2float(acch[j][3]);
            if (kg == 0) {
                pr.x += bias4.x; pr.y += bias4.y;
                pr.z += bias4.z; pr.w += bias4.w;
            }
            part[((size_t)j * 4 + kg) * NH + u] = pr;
        }
        __syncthreads();

        // ---- reduce + pointwise for 2 cells: batches kg and kg+4 ----
        __half* nv = v + (size_t)(1 - p) * 8 * KP;
#pragma unroll
        for (int cell = 0; cell < 2; ++cell) {
            const int j = kg + cell * 4;
            float4 s0 = part[((size_t)j * 4 + 0) * NH + u];
            float4 s1 = part[((size_t)j * 4 + 1) * NH + u];
            float4 s2 = part[((size_t)j * 4 + 2) * NH + u];
            float4 s3 = part[((size_t)j * 4 + 3) * NH + u];
            float gi = (s0.x + s1.x) + (s2.x + s3.x);
            float gf = (s0.y + s1.y) + (s2.y + s3.y);
            float gg = (s0.z + s1.z) + (s2.z + s3.z);
            float go = (s0.w + s1.w) + (s2.w + s3.w);
            float ii = fast_sig(gi);
            float ff = fast_sig(gf);
            float g2 = fast_tanh(gg);
            float oo = fast_sig(go);
            float cn = fmaf(ff, cst[cell], ii * g2);
            cst[cell] = cn;
            float hn = oo * fast_tanh(cn);

            nv[(size_t)j * KP + DIN + u] = __float2half(hn);
            if (hout)
                hout[((size_t)(b0 + j) * NT + t) * NH + u] = __float2half(hn);
            if (hlast && t == NT - 1)
                hlast[(b0 + j) * NH + u] = hn;
        }

        // ---- write prefetched x_{t+1} into next buffer ----
        if (DIN == 128) {
            if (havex)
                reinterpret_cast<__half2*>(nv)[(size_t)xb * KK + xk] = xrh;
        } else {
            if (havex && tid < 8 * DIN)
                nv[(size_t)xb * KP + xk] = __float2half(xrf);
        }

        __syncthreads();
        p ^= 1;
    }
}

// ---------------- final FC on last timestep of layer 2 ----------------
__global__ void fc_kernel(const float* __restrict__ fc_w,
                          const float* __restrict__ fc_b,
                          float* __restrict__ out)
{
    int b = blockIdx.x;
    int tid = threadIdx.x;           // 128 threads, one per unit
    float p = g_hlast[b * NH + tid] * fc_w[tid];
#pragma unroll
    for (int o = 16; o; o >>= 1) p += __shfl_down_sync(0xffffffffu, p, o);
    __shared__ float ws[4];
    if ((tid & 31) == 0) ws[tid >> 5] = p;
    __syncthreads();
    if (tid == 0) out[b] = ws[0] + ws[1] + ws[2] + ws[3] + fc_b[0];
}

// ---------------- launch ----------------
extern "C" void kernel_launch(void* const* d_in, const int* in_sizes, int n_in,
                              void* d_out, int out_size)
{
    const float* x    = (const float*)d_in[0];
    const float* wih0 = (const float*)d_in[1];
    const float* whh0 = (const float*)d_in[2];
    const float* bih0 = (const float*)d_in[3];
    const float* bhh0 = (const float*)d_in[4];
    const float* wih1 = (const float*)d_in[5];
    const float* whh1 = (const float*)d_in[6];
    const float* bih1 = (const float*)d_in[7];
    const float* bhh1 = (const float*)d_in[8];
    const float* wih2 = (const float*)d_in[9];
    const float* whh2 = (const float*)d_in[10];
    const float* bih2 = (const float*)d_in[11];
    const float* bhh2 = (const float*)d_in[12];
    const float* fcw  = (const float*)d_in[13];
    const float* fcb  = (const float*)d_in[14];
    float* out = (float*)d_out;

    void *ph0 = nullptr, *ph1 = nullptr, *phl = nullptr;
    cudaGetSymbolAddress(&ph0, g_h0);
    cudaGetSymbolAddress(&ph1, g_h1);
    cudaGetSymbolAddress(&phl, g_hlast);

    // dynamic smem: v[2][8][KP] halves + part[8][4][128] float4
    const int smem0 = 2 * 8 * 160 * 2 + 8 * 4 * 128 * 16;   // 5120 + 65536
    const int smem1 = 2 * 8 * 256 * 2 + 8 * 4 * 128 * 16;   // 8192 + 65536
    cudaFuncSetAttribute((const void*)lstm_layer_kernel<6, 160>,
                         cudaFuncAttributeMaxDynamicSharedMemorySize, smem0);
    cudaFuncSetAttribute((const void*)lstm_layer_kernel<128, 256>,
                         cudaFuncAttributeMaxDynamicSharedMemorySize, smem1);

    prep_kernel<<<132, 256>>>(wih0, whh0, bih0, bhh0, 0, 6,   160);
    prep_kernel<<<132, 256>>>(wih1, whh1, bih1, bhh1, 1, 128, 256);
    prep_kernel<<<132, 256>>>(wih2, whh2, bih2, bhh2, 2, 128, 256);

    lstm_layer_kernel<6, 160>  <<<NB / 8, 512, smem0>>>(x, (__half*)ph0, nullptr, 0);
    lstm_layer_kernel<128, 256><<<NB / 8, 512, smem1>>>(ph0, (__half*)ph1, nullptr, 1);
    lstm_layer_kernel<128, 256><<<NB / 8, 512, smem1>>>(ph1, nullptr, (float*)phl, 2);

    fc_kernel<<<NB, 128>>>(fcw, fcb, out);
}

// round 8
// speedup vs baseline: 3.8842x; 1.3814x over previous
#include <cuda_runtime.h>
#include <cuda_fp16.h>
#include <cstdint>
#include <cstddef>

#define NB 1024
#define NT 512
#define NH 128
#define BT (NB * NT)

// ---------------- scratch (device globals; no runtime allocation) ----------------
__device__ __half g_h0[(size_t)NB * NT * NH];   // layer0 out fp16 [B][T][H]
__device__ __half g_h1[(size_t)NB * NT * NH];   // layer1 out fp16 [B][T][H]
__device__ float  g_hlast[NB * NH];             // layer2 last h (fp32)
__device__ float  g_xp[(size_t)BT * 512];       // x-projection (reused per layer)
__device__ __half g_WTh[3][64 * NH * 8];        // recurrent w_hh packed [kk][u][8]
__device__ __half g_WF[2][65536];               // mma frag-packed w_ih (layers 1,2)
__device__ float  g_biasxp[3][512];             // per-layer bias (c = u*4+q order)
__device__ float  g_w0p[512 * 8];               // layer0 w_ih packed [c][8] (k<6)

// ---------------- activations ----------------
__device__ __forceinline__ float fast_tanh(float x) {
    float y;
    asm("tanh.approx.f32 %0, %1;" : "=f"(y) : "f"(x));
    return y;
}
__device__ __forceinline__ float fast_sig(float x) {
    return fmaf(0.5f, fast_tanh(0.5f * x), 0.5f);
}
__device__ __forceinline__ uint32_t smem_u32(const void* p) {
    uint32_t a;
    asm("{ .reg .u64 t; cvta.to.shared.u64 t, %1; cvt.u32.u64 %0, t; }" : "=r"(a) : "l"(p));
    return a;
}

// ---------------- prep: recurrent w_hh pack ----------------
// WTh[kk][u][8]: h8 -> q = h8>>1, par = h8&1; k = 2kk+par; val = w_hh[(q*128+u)][k]
__global__ void prep_rec_kernel(const float* __restrict__ w_hh, __half* __restrict__ WT)
{
    for (int idx = blockIdx.x * blockDim.x + threadIdx.x; idx < 64 * NH * 8;
         idx += gridDim.x * blockDim.x) {
        int h8 = idx & 7;
        int u  = (idx >> 3) & 127;
        int kk = idx >> 10;
        int q = h8 >> 1, par = h8 & 1;
        int k = 2 * kk + par;
        WT[idx] = __float2half(w_hh[(q * NH + u) * NH + k]);
    }
}

// ---------------- prep: mma B-frag pack (layers 1,2) + bias ----------------
// WF flat half idx: h4 = idx&3, lane = (idx>>2)&31, ks = (idx>>7)&7, cb = idx>>10
// c = cb*8 + lane/4; k = ks*16 + (lane&3)*2 + (h4&1) + (h4>>1)*8; val = w_ih[g][k]
__global__ void prep_mma_kernel(const float* __restrict__ w_ih,
                                const float* __restrict__ b_ih,
                                const float* __restrict__ b_hh,
                                __half* __restrict__ WF, float* __restrict__ bias)
{
    for (int idx = blockIdx.x * blockDim.x + threadIdx.x; idx < 65536;
         idx += gridDim.x * blockDim.x) {
        int h4   = idx & 3;
        int lane = (idx >> 2) & 31;
        int ks   = (idx >> 7) & 7;
        int cb   = idx >> 10;
        int c = cb * 8 + (lane >> 2);
        int q = c & 3, u = c >> 2;
        int g = q * NH + u;
        int k = ks * 16 + (lane & 3) * 2 + (h4 & 1) + (h4 >> 1) * 8;
        WF[idx] = __float2half(w_ih[g * NH + k]);
    }
    for (int c = blockIdx.x * blockDim.x + threadIdx.x; c < 512;
         c += gridDim.x * blockDim.x) {
        int q = c & 3, u = c >> 2;
        int g = q * NH + u;
        bias[c] = b_ih[g] + b_hh[g];
    }
}

// ---------------- prep: layer0 w_ih pack (K=6) + bias ----------------
__global__ void prep_l0_kernel(const float* __restrict__ w_ih,
                               const float* __restrict__ b_ih,
                               const float* __restrict__ b_hh,
                               float* __restrict__ w0p, float* __restrict__ bias)
{
    for (int idx = blockIdx.x * blockDim.x + threadIdx.x; idx < 512 * 8;
         idx += gridDim.x * blockDim.x) {
        int k = idx & 7, c = idx >> 3;
        int q = c & 3, u = c >> 2;
        int g = q * NH + u;
        w0p[idx] = (k < 6) ? w_ih[g * 6 + k] : 0.0f;
    }
    for (int c = blockIdx.x * blockDim.x + threadIdx.x; c < 512;
         c += gridDim.x * blockDim.x) {
        int q = c & 3, u = c >> 2;
        int g = q * NH + u;
        bias[c] = b_ih[g] + b_hh[g];
    }
}

// ---------------- layer0 x-projection (scalar, K=6) ----------------
// XP[row][c] = bias[c] + sum_{k<6} w0p[c][k] * x[row][k], row = b*NT+t
__global__ void __launch_bounds__(512, 1)
xp0_kernel(const float* __restrict__ x, const float* __restrict__ w0p,
           const float* __restrict__ bias, float* __restrict__ XP)
{
    __shared__ __align__(16) float xs[128 * 8];
    const int tid = threadIdx.x;
    const size_t row0 = (size_t)blockIdx.x * 128;

    for (int i = tid; i < 1024; i += 512) {
        int r = i >> 3, k = i & 7;
        xs[i] = (k < 6) ? x[(row0 + r) * 6 + k] : 0.0f;
    }
    __syncthreads();

    const int c = tid;   // 512 cols
    float4 w01 = *reinterpret_cast<const float4*>(&w0p[c * 8]);
    float4 w23 = *reinterpret_cast<const float4*>(&w0p[c * 8 + 4]);
    float bc = bias[c];
    for (int r = 0; r < 128; ++r) {
        float4 x01 = *reinterpret_cast<const float4*>(&xs[r * 8]);
        float2 x2  = *reinterpret_cast<const float2*>(&xs[r * 8 + 4]);
        float s = bc;
        s = fmaf(w01.x, x01.x, s);
        s = fmaf(w01.y, x01.y, s);
        s = fmaf(w01.z, x01.z, s);
        s = fmaf(w01.w, x01.w, s);
        s = fmaf(w23.x, x2.x, s);
        s = fmaf(w23.y, x2.y, s);
        XP[(row0 + r) * 512 + c] = s;
    }
}

// ---------------- layers 1,2 x-projection via mma.sync ----------------
// XP[row][c] = bias[c] + sum_k w_ih[g][k] * h_prev[row][k]; M=BT, N=512, K=128
// CTA tile: M=128, N=256 (grid.y selects N-half); 16 warps = 4(m) x 4(n);
// warp tile M=32 (2 m16), N=64 (8 n8); A via ldmatrix from padded smem,
// B streamed gmem->regs in pre-packed frag order.
__global__ void __launch_bounds__(512, 1)
xp_mma_kernel(const __half* __restrict__ X, const __half* __restrict__ WF,
              const float* __restrict__ bias, float* __restrict__ XP)
{
    __shared__ __align__(16) __half xs[128 * 136];
    const int tid  = threadIdx.x;
    const int wid  = tid >> 5;
    const int lane = tid & 31;
    const size_t row0 = (size_t)blockIdx.x * 128;
    const int ny = blockIdx.y;

    // stage A tile (padded row stride 136 halves = 17 uint4, conflict-free ldmatrix)
    for (int i = tid; i < 2048; i += 512) {
        int r = i >> 4, cvec = i & 15;
        reinterpret_cast<uint4*>(xs)[r * 17 + cvec] =
            reinterpret_cast<const uint4*>(X + (row0 + r) * NH)[cvec];
    }
    __syncthreads();

    const int wm = wid & 3;
    const int wn = wid >> 2;
    const int cb0 = ny * 32 + wn * 8;       // this warp's 8 n8-tiles (global col/8)
    const uint2* __restrict__ WFp = reinterpret_cast<const uint2*>(WF);

    // ldmatrix lane address pieces
    const int lrow = (lane & 7) + ((lane >> 3) & 1) * 8;   // row within m16
    const int kadd = (lane >> 4) * 8;                      // +8 k for segs 2,3
    const uint32_t xsb = smem_u32(xs);

    float acc[2][8][4];
#pragma unroll
    for (int mt = 0; mt < 2; ++mt)
#pragma unroll
        for (int nt = 0; nt < 8; ++nt)
#pragma unroll
            for (int i = 0; i < 4; ++i) acc[mt][nt][i] = 0.0f;

#pragma unroll
    for (int ks = 0; ks < 8; ++ks) {
        uint2 b[8];
#pragma unroll
        for (int nt = 0; nt < 8; ++nt)
            b[nt] = WFp[(size_t)((cb0 + nt) * 8 + ks) * 32 + lane];

#pragma unroll
        for (int mt = 0; mt < 2; ++mt) {
            int row = wm * 32 + mt * 16 + lrow;
            uint32_t addr = xsb + (uint32_t)(row * 136 + ks * 16 + kadd) * 2;
            uint32_t a0, a1, a2, a3;
            asm volatile("ldmatrix.sync.aligned.m8n8.x4.shared.b16 {%0,%1,%2,%3}, [%4];"
                         : "=r"(a0), "=r"(a1), "=r"(a2), "=r"(a3) : "r"(addr));
#pragma unroll
            for (int nt = 0; nt < 8; ++nt) {
                asm volatile(
                    "mma.sync.aligned.m16n8k16.row.col.f32.f16.f16.f32 "
                    "{%0,%1,%2,%3}, {%4,%5,%6,%7}, {%8,%9}, {%0,%1,%2,%3};"
                    : "+f"(acc[mt][nt][0]), "+f"(acc[mt][nt][1]),
                      "+f"(acc[mt][nt][2]), "+f"(acc[mt][nt][3])
                    : "r"(a0), "r"(a1), "r"(a2), "r"(a3),
                      "r"(b[nt].x), "r"(b[nt].y));
            }
        }
    }

    // epilogue: add bias, store fp32
    const int gp = lane >> 2, tig = lane & 3;
#pragma unroll
    for (int mt = 0; mt < 2; ++mt) {
#pragma unroll
        for (int nt = 0; nt < 8; ++nt) {
            size_t row = row0 + wm * 32 + mt * 16 + gp;
            int col = ny * 256 + wn * 64 + nt * 8 + tig * 2;
            float2 bb = *reinterpret_cast<const float2*>(&bias[col]);
            float2 o0 = make_float2(acc[mt][nt][0] + bb.x, acc[mt][nt][1] + bb.y);
            float2 o1 = make_float2(acc[mt][nt][2] + bb.x, acc[mt][nt][3] + bb.y);
            *reinterpret_cast<float2*>(&XP[row * 512 + col]) = o0;
            *reinterpret_cast<float2*>(&XP[(row + 8) * 512 + col]) = o1;
        }
    }
}

// ---------------- recurrent LSTM layer (K=128, HFMA2, xp prefetched) ----------
// One CTA = 8 batches, 512 thr = 128 u x 4 k-groups (32 k each, disjoint).
// fp16 accumulate over full group K; single convert; smem partials reduce.
__global__ void __launch_bounds__(512, 1)
rec_kernel(const float* __restrict__ xp,      // [BT][512] bias included
           const __half* __restrict__ WTh,    // [64][128][8]
           __half* __restrict__ hout,         // [B][T][128] or nullptr
           float* __restrict__ hlast)         // [B][128] or nullptr
{
    extern __shared__ __align__(16) char smd[];
    __half* v = reinterpret_cast<__half*>(smd);                       // [2][8][128]
    float4* part = reinterpret_cast<float4*>(smd + 2 * 8 * NH * 2);   // [8][4][128]

    const uint4* __restrict__ W4 = reinterpret_cast<const uint4*>(WTh);

    const int tid = threadIdx.x;
    const int u   = tid & 127;
    const int kg  = tid >> 7;            // 0..3
    const int b0  = blockIdx.x * 8;
    const int kb0 = kg * 16;             // kk base (16 kk = 32 k)

    for (int i = tid; i < 1024; i += 512) reinterpret_cast<uint32_t*>(v)[i] = 0u;
    __syncthreads();

    float cst[2] = {0.f, 0.f};
    int p = 0;

    for (int t = 0; t < NT; ++t) {
        // prefetch xp for this thread's 2 cells (consumed after the sync)
        float4 xpv0 = *reinterpret_cast<const float4*>(
            &xp[((size_t)(b0 + kg) * NT + t) * 512 + u * 4]);
        float4 xpv1 = *reinterpret_cast<const float4*>(
            &xp[((size_t)(b0 + kg + 4) * NT + t) * 512 + u * 4]);

        // fp16 partial gates over group's 32 k, all 8 batches
        __half2 acch[8][4];
#pragma unroll
        for (int j = 0; j < 8; ++j)
#pragma unroll
            for (int q = 0; q < 4; ++q) acch[j][q] = __float2half2_rn(0.f);

        const __half* vp = v + (size_t)p * 8 * NH;

#pragma unroll
        for (int blk = 0; blk < 4; ++blk) {
            const int kkb = kb0 + blk * 4;
            uint4 wv0 = W4[(size_t)(kkb + 0) * NH + u];
            uint4 wv1 = W4[(size_t)(kkb + 1) * NH + u];
            uint4 wv2 = W4[(size_t)(kkb + 2) * NH + u];
            uint4 wv3 = W4[(size_t)(kkb + 3) * NH + u];
            const __half2* w0 = reinterpret_cast<const __half2*>(&wv0);
            const __half2* w1 = reinterpret_cast<const __half2*>(&wv1);
            const __half2* w2 = reinterpret_cast<const __half2*>(&wv2);
            const __half2* w3 = reinterpret_cast<const __half2*>(&wv3);
#pragma unroll
            for (int j = 0; j < 8; ++j) {
                uint4 xv = *reinterpret_cast<const uint4*>(vp + (size_t)j * NH + 2 * kkb);
                const __half2* xpr = reinterpret_cast<const __half2*>(&xv);
#pragma unroll
                for (int q = 0; q < 4; ++q) {
                    acch[j][q] = __hfma2(w0[q], xpr[0], acch[j][q]);
                    acch[j][q] = __hfma2(w1[q], xpr[1], acch[j][q]);
                    acch[j][q] = __hfma2(w2[q], xpr[2], acch[j][q]);
                    acch[j][q] = __hfma2(w3[q], xpr[3], acch[j][q]);
                }
            }
        }

        // single convert + partial write
#pragma unroll
        for (int j = 0; j < 8; ++j) {
            float4 pr;
            pr.x = __low2float(acch[j][0]) + __high2float(acch[j][0]);
            pr.y = __low2float(acch[j][1]) + __high2float(acch[j][1]);
            pr.z = __low2float(acch[j][2]) + __high2float(acch[j][2]);
            pr.w = __low2float(acch[j][3]) + __high2float(acch[j][3]);
            part[((size_t)j * 4 + kg) * NH + u] = pr;
        }
        __syncthreads();

        // reduce + pointwise for 2 cells
        __half* nv = v + (size_t)(1 - p) * 8 * NH;
#pragma unroll
        for (int cell = 0; cell < 2; ++cell) {
            const int j = kg + cell * 4;
            const float4 xpv = cell ? xpv1 : xpv0;
            float4 s0 = part[((size_t)j * 4 + 0) * NH + u];
            float4 s1 = part[((size_t)j * 4 + 1) * NH + u];
            float4 s2 = part[((size_t)j * 4 + 2) * NH + u];
            float4 s3 = part[((size_t)j * 4 + 3) * NH + u];
            float gi = xpv.x + (s0.x + s1.x) + (s2.x + s3.x);
            float gf = xpv.y + (s0.y + s1.y) + (s2.y + s3.y);
            float gg = xpv.z + (s0.z + s1.z) + (s2.z + s3.z);
            float go = xpv.w + (s0.w + s1.w) + (s2.w + s3.w);
            float ii = fast_sig(gi);
            float ff = fast_sig(gf);
            float gz = fast_tanh(gg);
            float oo = fast_sig(go);
            float cn = fmaf(ff, cst[cell], ii * gz);
            cst[cell] = cn;
            float hn = oo * fast_tanh(cn);

            nv[(size_t)j * NH + u] = __float2half(hn);
            if (hout)
                hout[((size_t)(b0 + j) * NT + t) * NH + u] = __float2half(hn);
            if (hlast && t == NT - 1)
                hlast[(b0 + j) * NH + u] = hn;
        }
        __syncthreads();
        p ^= 1;
    }
}

// ---------------- final FC on last timestep of layer 2 ----------------
__global__ void fc_kernel(const float* __restrict__ fc_w,
                          const float* __restrict__ fc_b,
                          float* __restrict__ out)
{
    int b = blockIdx.x;
    int tid = threadIdx.x;           // 128 threads
    float p = g_hlast[b * NH + tid] * fc_w[tid];
#pragma unroll
    for (int o = 16; o; o >>= 1) p += __shfl_down_sync(0xffffffffu, p, o);
    __shared__ float ws[4];
    if ((tid & 31) == 0) ws[tid >> 5] = p;
    __syncthreads();
    if (tid == 0) out[b] = ws[0] + ws[1] + ws[2] + ws[3] + fc_b[0];
}

// ---------------- launch ----------------
extern "C" void kernel_launch(void* const* d_in, const int* in_sizes, int n_in,
                              void* d_out, int out_size)
{
    const float* x    = (const float*)d_in[0];
    const float* wih0 = (const float*)d_in[1];
    const float* whh0 = (const float*)d_in[2];
    const float* bih0 = (const float*)d_in[3];
    const float* bhh0 = (const float*)d_in[4];
    const float* wih1 = (const float*)d_in[5];
    const float* whh1 = (const float*)d_in[6];
    const float* bih1 = (const float*)d_in[7];
    const float* bhh1 = (const float*)d_in[8];
    const float* wih2 = (const float*)d_in[9];
    const float* whh2 = (const float*)d_in[10];
    const float* bih2 = (const float*)d_in[11];
    const float* bhh2 = (const float*)d_in[12];
    const float* fcw  = (const float*)d_in[13];
    const float* fcb  = (const float*)d_in[14];
    float* out = (float*)d_out;

    void *ph0, *ph1, *phl, *pxp, *pwt, *pwf, *pbias, *pw0;
    cudaGetSymbolAddress(&ph0, g_h0);
    cudaGetSymbolAddress(&ph1, g_h1);
    cudaGetSymbolAddress(&phl, g_hlast);
    cudaGetSymbolAddress(&pxp, g_xp);
    cudaGetSymbolAddress(&pwt, g_WTh);
    cudaGetSymbolAddress(&pwf, g_WF);
    cudaGetSymbolAddress(&pbias, g_biasxp);
    cudaGetSymbolAddress(&pw0, g_w0p);

    __half* h0   = (__half*)ph0;
    __half* h1   = (__half*)ph1;
    float*  hl   = (float*)phl;
    float*  xp   = (float*)pxp;
    __half* WT   = (__half*)pwt;
    __half* WF   = (__half*)pwf;
    float*  bs   = (float*)pbias;
    float*  w0p  = (float*)pw0;

    const int rec_smem = 2 * 8 * NH * 2 + 8 * 4 * NH * 16;   // 2048 + 65536
    cudaFuncSetAttribute((const void*)rec_kernel,
                         cudaFuncAttributeMaxDynamicSharedMemorySize, rec_smem);

    // prep
    prep_l0_kernel <<<64, 256>>>(wih0, bih0, bhh0, w0p, bs + 0 * 512);
    prep_rec_kernel<<<132, 256>>>(whh0, WT + 0 * 65536);
    prep_mma_kernel<<<132, 256>>>(wih1, bih1, bhh1, WF + 0 * 65536, bs + 1 * 512);
    prep_rec_kernel<<<132, 256>>>(whh1, WT + 1 * 65536);
    prep_mma_kernel<<<132, 256>>>(wih2, bih2, bhh2, WF + 1 * 65536, bs + 2 * 512);
    prep_rec_kernel<<<132, 256>>>(whh2, WT + 2 * 65536);

    // layer 0
    xp0_kernel<<<BT / 128, 512>>>(x, w0p, bs + 0 * 512, xp);
    rec_kernel<<<NB / 8, 512, rec_smem>>>(xp, WT + 0 * 65536, h0, nullptr);

    // layer 1
    {
        dim3 g(BT / 128, 2);
        xp_mma_kernel<<<g, 512>>>(h0, WF + 0 * 65536, bs + 1 * 512, xp);
    }
    rec_kernel<<<NB / 8, 512, rec_smem>>>(xp, WT + 1 * 65536, h1, nullptr);

    // layer 2
    {
        dim3 g(BT / 128, 2);
        xp_mma_kernel<<<g, 512>>>(h1, WF + 1 * 65536, bs + 2 * 512, xp);
    }
    rec_kernel<<<NB / 8, 512, rec_smem>>>(xp, WT + 2 * 65536, nullptr, hl);

    fc_kernel<<<NB, 128>>>(fcw, fcb, out);
}